// round 3
// baseline (speedup 1.0000x reference)
#include <cuda_runtime.h>
#include <cstdint>

#define NF    40960
#define MDIM  256
#define NB    2048
#define ROWS  (2*NB)          // 4096 feature rows (white then black)
#define PARTS 2               // warps per row
#define HALF_VEC4 5120        // float4s per half row (10240/2)
#define BATCH 8               // float4s per lane per batch (= 32 floats)
#define NBATCH (HALF_VEC4/32/BATCH)  // 20 batches per half-row warp

// Transposed feature-transformer weights: ft_wT[f][m], 40960 x 256 fp32 = 41.9 MB
__device__ float g_ftwT[NF * MDIM];
// Partial accumulators: [part][row][m]  (2 x 4096 x 256 fp32 = 8 MB)
__device__ float g_acc[PARTS * ROWS * MDIM];

// ---------------------------------------------------------------------------
// Kernel 1: tiled transpose ft_w [256, 40960] -> g_ftwT [40960, 256]
// float4 loads and stores; conflict-free 32x33 shared tile.
// ---------------------------------------------------------------------------
__global__ __launch_bounds__(256) void transpose_ftw_kernel(const float* __restrict__ ft_w) {
    __shared__ float tile[32][33];
    const int f0 = blockIdx.x * 32;
    const int m0 = blockIdx.y * 32;
    const int t  = threadIdx.x;

    {   // load: thread t -> row m = t>>3, quad q = t&7 (float4 along f)
        const int m = t >> 3;
        const int q = t & 7;
        const float4 v = *reinterpret_cast<const float4*>(
            ft_w + (size_t)(m0 + m) * NF + f0 + q * 4);
        tile[m][q * 4 + 0] = v.x;
        tile[m][q * 4 + 1] = v.y;
        tile[m][q * 4 + 2] = v.z;
        tile[m][q * 4 + 3] = v.w;
    }
    __syncthreads();
    {   // store: thread t -> row f = t>>3, quad m4 = t&7 (float4 along m)
        const int f  = t >> 3;
        const int m4 = t & 7;
        float4 v;
        v.x = tile[m4 * 4 + 0][f];
        v.y = tile[m4 * 4 + 1][f];
        v.z = tile[m4 * 4 + 2][f];
        v.w = tile[m4 * 4 + 3][f];
        // transposed indices: tile[m][f] -> out[f][m]
        *reinterpret_cast<float4*>(
            g_ftwT + (size_t)(f0 + f) * MDIM + m0 + m4 * 4) = v;
    }
}

// ---------------------------------------------------------------------------
// Kernel 2: fused sparse scan + gather-accumulate, software-pipelined.
// One warp per (row, half). Lane l accumulates m=4l..4l+3 and m=128+4l..131+4l.
// Per batch: build 32-bit nonzero mask from 8 float4s (v then dead),
// immediately issue next batch's loads, THEN do ballot + gathers.
// ---------------------------------------------------------------------------
__global__ __launch_bounds__(256) void scan_accum_kernel(
    const float* __restrict__ wf,
    const float* __restrict__ bfeat)
{
    const int gw   = (blockIdx.x * blockDim.x + threadIdx.x) >> 5;  // 0..8191
    const int lane = threadIdx.x & 31;
    const int row  = gw >> 1;           // 0..4095
    const int part = gw & 1;

    const float* rowp = (row < NB) ? (wf + (size_t)row * NF)
                                   : (bfeat + (size_t)(row - NB) * NF);
    const float4* p = reinterpret_cast<const float4*>(rowp) + part * HALF_VEC4;
    const int fbase_part = part * (HALF_VEC4 * 4);

    float4 acc0 = make_float4(0.f, 0.f, 0.f, 0.f);
    float4 acc1 = make_float4(0.f, 0.f, 0.f, 0.f);

    float4 v[BATCH];
    #pragma unroll
    for (int u = 0; u < BATCH; u++)
        v[u] = __ldcs(&p[u * 32 + lane]);

    #pragma unroll 1
    for (int bt = 0; bt < NBATCH; bt++) {
        // 1) build per-lane nonzero mask; bit (u*4+c) = component c of float4 u
        unsigned mask = 0u;
        #pragma unroll
        for (int u = 0; u < BATCH; u++) {
            if (v[u].x != 0.0f) mask |= 1u << (u * 4 + 0);
            if (v[u].y != 0.0f) mask |= 1u << (u * 4 + 1);
            if (v[u].z != 0.0f) mask |= 1u << (u * 4 + 2);
            if (v[u].w != 0.0f) mask |= 1u << (u * 4 + 3);
        }

        // 2) v is dead: issue next batch's loads NOW (overlap with gathers)
        if (bt + 1 < NBATCH) {
            #pragma unroll
            for (int u = 0; u < BATCH; u++)
                v[u] = __ldcs(&p[(bt + 1) * BATCH * 32 + u * 32 + lane]);
        }

        // 3) process nonzeros via one ballot + mask shuffles
        unsigned bal = __ballot_sync(0xffffffffu, mask != 0u);
        const int base0 = fbase_part + bt * BATCH * 128;
        while (bal) {
            const int s = __ffs(bal) - 1;
            bal &= bal - 1u;
            unsigned sm = __shfl_sync(0xffffffffu, mask, s);
            do {
                const int b = __ffs(sm) - 1;
                sm &= sm - 1u;
                const int f = base0 + (b >> 2) * 128 + s * 4 + (b & 3);
                const float4* wrow =
                    reinterpret_cast<const float4*>(g_ftwT + (size_t)f * MDIM);
                const float4 w0 = wrow[lane];
                const float4 w1 = wrow[32 + lane];
                acc0.x += w0.x; acc0.y += w0.y; acc0.z += w0.z; acc0.w += w0.w;
                acc1.x += w1.x; acc1.y += w1.y; acc1.z += w1.z; acc1.w += w1.w;
            } while (sm);
        }
    }

    float4* outp = reinterpret_cast<float4*>(g_acc + ((size_t)part * ROWS + row) * MDIM);
    outp[lane]      = acc0;
    outp[32 + lane] = acc1;
}

// ---------------------------------------------------------------------------
// Kernel 3: combine partials + bias, stm blend + clip, MLP 512->32->32->1
// ---------------------------------------------------------------------------
__device__ __forceinline__ float clamp01(float x) {
    return fminf(fmaxf(x, 0.0f), 1.0f);
}

__global__ __launch_bounds__(256) void mlp_tail_kernel(
    const float* __restrict__ stm,
    const float* __restrict__ ft_b,
    const float* __restrict__ l1_w,
    const float* __restrict__ l1_b,
    const float* __restrict__ l2_w,
    const float* __restrict__ l2_b,
    const float* __restrict__ l3_w,
    const float* __restrict__ l3_b,
    float* __restrict__ out)
{
    const int b   = blockIdx.x;
    const int tid = threadIdx.x;

    __shared__ float s_h[512];
    __shared__ float s_l2x[32];

    const float bias = ft_b[tid];
    const float accW = g_acc[(size_t)b * MDIM + tid]
                     + g_acc[((size_t)ROWS + b) * MDIM + tid] + bias;
    const float accB = g_acc[((size_t)NB + b) * MDIM + tid]
                     + g_acc[((size_t)ROWS + NB + b) * MDIM + tid] + bias;

    const float s  = stm[b];
    s_h[tid]       = clamp01(s * accW + (1.0f - s) * accB);
    s_h[256 + tid] = clamp01(s * accB + (1.0f - s) * accW);
    __syncthreads();

    // L1: 512 -> 32. Output n = tid>>3; 8 threads per output.
    {
        const int n   = tid >> 3;
        const int seg = tid & 7;
        const float4* wrow = reinterpret_cast<const float4*>(l1_w + n * 512 + seg * 64);
        const float4* hv   = reinterpret_cast<const float4*>(s_h) + seg * 16;
        float psum = 0.0f;
        #pragma unroll
        for (int i = 0; i < 16; i++) {
            const float4 a = wrow[i];
            const float4 x = hv[i];
            psum += a.x * x.x;
            psum += a.y * x.y;
            psum += a.z * x.z;
            psum += a.w * x.w;
        }
        psum += __shfl_down_sync(0xffffffffu, psum, 4);
        psum += __shfl_down_sync(0xffffffffu, psum, 2);
        psum += __shfl_down_sync(0xffffffffu, psum, 1);
        if (seg == 0) s_l2x[n] = clamp01(psum + l1_b[n]);
    }
    __syncthreads();

    // L2 (32->32), L3 (32->1), eval scaling. Warp 0 only.
    if (tid < 32) {
        float q = l2_b[tid];
        #pragma unroll
        for (int k = 0; k < 32; k++) q += l2_w[tid * 32 + k] * s_l2x[k];
        const float l3x = clamp01(q);
        float t = l3x * l3_w[tid];
        #pragma unroll
        for (int off = 16; off > 0; off >>= 1)
            t += __shfl_down_sync(0xffffffffu, t, off);
        if (tid == 0) {
            const float ev = clamp01(t + l3_b[0]);
            out[b] = (ev - 0.5f) * 2.0f * 10000.0f;
        }
    }
}

// ---------------------------------------------------------------------------
// Launch
// ---------------------------------------------------------------------------
extern "C" void kernel_launch(void* const* d_in, const int* in_sizes, int n_in,
                              void* d_out, int out_size)
{
    const float* wf    = (const float*)d_in[0];
    const float* bfeat = (const float*)d_in[1];
    const float* stm   = (const float*)d_in[2];
    const float* ft_w  = (const float*)d_in[3];
    const float* ft_b  = (const float*)d_in[4];
    const float* l1_w  = (const float*)d_in[5];
    const float* l1_b  = (const float*)d_in[6];
    const float* l2_w  = (const float*)d_in[7];
    const float* l2_b  = (const float*)d_in[8];
    const float* l3_w  = (const float*)d_in[9];
    const float* l3_b  = (const float*)d_in[10];
    float* out = (float*)d_out;

    // 1) Transpose ft_w -> g_ftwT (L2-resident gather table)
    dim3 tgrid(NF / 32, MDIM / 32);
    transpose_ftw_kernel<<<tgrid, 256>>>(ft_w);

    // 2) Fused sparse scan + gather: 8192 warps (one per half-row)
    const int total_warps = ROWS * PARTS;              // 8192
    scan_accum_kernel<<<total_warps / 8, 256>>>(wf, bfeat);

    // 3) Blend + MLP tail
    mlp_tail_kernel<<<NB, 256>>>(stm, ft_b, l1_w, l1_b, l2_w, l2_b,
                                 l3_w, l3_b, out);
}